// round 7
// baseline (speedup 1.0000x reference)
#include <cuda_runtime.h>
#include <math.h>
#include <stdint.h>

typedef unsigned long long u64;

#define MSG_DIM 100
#define MEM_DIM 172
#define KDIM    272          // MSG_DIM + MEM_DIM
#define JPAD    176          // MEM_DIM padded
#define ROWS    16           // update rows per block
#define NTHREADS 192
#define XS      20           // xT row stride (floats), 16B-aligned
#define TK      8            // weight k-tile
#define NT      (KDIM / TK)  // 34 tiles
#define KROW    528          // floats per k in packed weights: 176*2 (rz) + 176 (n)
#define TILE_F  (TK * KROW)  // 4224 floats = 16896 B per tile

// ---------------------------------------------------------------------------
// Persistent scratch: packed weights, K-major.
// Per k: [ {wr,wz} x 176 | wn x 176 ]  (528 floats). ~574 KB total.
// ---------------------------------------------------------------------------
__device__ __align__(16) float g_Wt[KDIM * KROW];
__device__ float g_bias[4 * JPAD];

// ---- packed fp32x2 helpers -------------------------------------------------
__device__ __forceinline__ u64 fma2(u64 b, u64 x, u64 c) {
    u64 d;
    asm("fma.rn.f32x2 %0, %1, %2, %3;" : "=l"(d) : "l"(b), "l"(x), "l"(c));
    return d;
}
__device__ __forceinline__ u64 dup2(float v) {
    u64 d; unsigned u = __float_as_uint(v);
    asm("mov.b64 %0, {%1, %1};" : "=l"(d) : "r"(u));
    return d;
}
__device__ __forceinline__ float2 unpack2(u64 d) {
    unsigned lo, hi;
    asm("mov.b64 {%0, %1}, %2;" : "=r"(lo), "=r"(hi) : "l"(d));
    return make_float2(__uint_as_float(lo), __uint_as_float(hi));
}
__device__ __forceinline__ uint32_t smem_u32(const void* p) {
    uint32_t a;
    asm("{ .reg .u64 t; cvta.to.shared.u64 t, %1; cvt.u32.u64 %0, t; }"
        : "=r"(a) : "l"(p));
    return a;
}
__device__ __forceinline__ void cp_async16(uint32_t saddr, const void* gaddr) {
    asm volatile("cp.async.cg.shared.global [%0], [%1], 16;" :: "r"(saddr), "l"(gaddr));
}

// ---------------------------------------------------------------------------
// Prep: repack W_ih [516,100], W_hh [516,172] into packed K-major tiles.
// ---------------------------------------------------------------------------
__global__ void prep_kernel(const float* __restrict__ W_ih,
                            const float* __restrict__ W_hh,
                            const float* __restrict__ b_ih,
                            const float* __restrict__ b_hh) {
    int idx = blockIdx.x * blockDim.x + threadIdx.x;
    if (idx < KDIM * JPAD) {
        int k = idx / JPAD;
        int j = idx - k * JPAD;
        float wr = 0.f, wz = 0.f, wn = 0.f;
        if (j < MEM_DIM) {
            if (k < MSG_DIM) {
                wr = W_ih[j * MSG_DIM + k];
                wz = W_ih[(MEM_DIM + j) * MSG_DIM + k];
                wn = W_ih[(2 * MEM_DIM + j) * MSG_DIM + k];
            } else {
                int kk = k - MSG_DIM;
                wr = W_hh[j * MEM_DIM + kk];
                wz = W_hh[(MEM_DIM + j) * MEM_DIM + kk];
                wn = W_hh[(2 * MEM_DIM + j) * MEM_DIM + kk];
            }
        }
        g_Wt[k * KROW + 2 * j + 0]       = wr;
        g_Wt[k * KROW + 2 * j + 1]       = wz;
        g_Wt[k * KROW + 2 * JPAD + j]    = wn;
    }
    if (idx < JPAD) {
        int j = idx;
        float br = 0.f, bz = 0.f, bi = 0.f, bh = 0.f;
        if (j < MEM_DIM) {
            br = b_ih[j]               + b_hh[j];
            bz = b_ih[MEM_DIM + j]     + b_hh[MEM_DIM + j];
            bi = b_ih[2 * MEM_DIM + j];
            bh = b_hh[2 * MEM_DIM + j];
        }
        g_bias[j]            = br;
        g_bias[JPAD + j]     = bz;
        g_bias[2 * JPAD + j] = bi;
        g_bias[3 * JPAD + j] = bh;
    }
}

// ---------------------------------------------------------------------------
// Passthrough copy (vectorized). Full occupancy, MLP-rich.
// ---------------------------------------------------------------------------
__global__ void copy_kernel(const float* __restrict__ src, float* __restrict__ dst, long long n) {
    long long i = (long long)blockIdx.x * blockDim.x + threadIdx.x;
    long long n4 = n >> 2;
    if (i < n4) ((float4*)dst)[i] = ((const float4*)src)[i];
    long long tail = n & 3;
    if (i < tail) dst[n4 * 4 + i] = src[n4 * 4 + i];
}

// ---------------------------------------------------------------------------
// GRU: weights staged through smem k-tiles (triple-buffered cp.async).
// Thread j (<172) owns output column j across 16 rows.
// Dynamic smem layout (floats):
//   [0, 3*TILE_F)                weight tile buffers (3 x 16896 B)
//   [3*TILE_F, +KDIM*XS)         xT transposed x
//   then 16 ints s_nid, 16 floats s_ts
// ---------------------------------------------------------------------------
#define SM_W   0
#define SM_XT  (3 * TILE_F)
#define SM_NID (SM_XT + KDIM * XS)
#define SM_TS  (SM_NID + ROWS)
#define SM_TOT ((SM_TS + ROWS) * 4)

__global__ void __launch_bounds__(NTHREADS, 3)
gru_kernel(const int*   __restrict__ node_ids,
           const float* __restrict__ messages,
           const float* __restrict__ timestamps,
           const float* __restrict__ memory,
           float*       __restrict__ out,
           int n_upd, long long n_nodes)
{
    extern __shared__ __align__(16) float sm[];
    float* __restrict__ wbuf = sm + SM_W;
    float* __restrict__ xT   = sm + SM_XT;
    int*   __restrict__ s_nid = (int*)(sm + SM_NID);
    float* __restrict__ s_ts  = sm + SM_TS;

    const int tid  = threadIdx.x;
    const int row0 = blockIdx.x * ROWS;
    const uint32_t wbase = smem_u32(wbuf);

    // ---- preload weight tiles 0 and 1 (groups 0,1) ----
    #pragma unroll 1
    for (int t0 = 0; t0 < 2; t0++) {
        const float* gsrc = g_Wt + t0 * TILE_F;
        uint32_t sdst = wbase + t0 * (TILE_F * 4);
        for (int i = tid; i < TILE_F / 4; i += NTHREADS)
            cp_async16(sdst + i * 16, gsrc + i * 4);
        asm volatile("cp.async.commit_group;");
    }

    if (tid < ROWS) {
        int r = row0 + tid;
        if (r < n_upd) { s_nid[tid] = node_ids[r]; s_ts[tid] = timestamps[r]; }
        else           { s_nid[tid] = -1;          s_ts[tid] = 0.f; }
    }
    __syncthreads();

    // ---- gather x = [msg | h] transposed into smem ----
    for (int idx = tid; idx < ROWS * KDIM; idx += NTHREADS) {
        int r = idx / KDIM;
        int k = idx - r * KDIM;
        float v = 0.f;
        int nid = s_nid[r];
        if (nid >= 0) {
            v = (k < MSG_DIM)
              ? messages[(size_t)(row0 + r) * MSG_DIM + k]
              : memory  [(size_t)nid * MEM_DIM + (k - MSG_DIM)];
        }
        xT[k * XS + r] = v;
    }
    __syncthreads();

    const int j = tid;

    u64 ar2[ROWS / 2], az2[ROWS / 2], ani2[ROWS / 2], anh2[ROWS / 2];
    {
        u64 z0 = dup2(0.f);
        #pragma unroll
        for (int p = 0; p < ROWS / 2; p++) { ar2[p] = z0; az2[p] = z0; ani2[p] = z0; anh2[p] = z0; }
    }

    // ---- main loop over weight k-tiles ----
    #pragma unroll 1
    for (int t = 0; t < NT; t++) {
        asm volatile("cp.async.wait_group 1;");
        __syncthreads();                       // tile t visible; buf (t+2)%3 free

        // prefetch tile t+2 into buffer (t+2)%3
        if (t + 2 < NT) {
            const float* gsrc = g_Wt + (t + 2) * TILE_F;
            uint32_t sdst = wbase + ((t + 2) % 3) * (TILE_F * 4);
            for (int i = tid; i < TILE_F / 4; i += NTHREADS)
                cp_async16(sdst + i * 16, gsrc + i * 4);
        }
        asm volatile("cp.async.commit_group;");

        if (j < JPAD) {
            const float* __restrict__ wb = wbuf + (t % 3) * TILE_F;
            const int k0 = t * TK;
            #pragma unroll
            for (int kk = 0; kk < TK; kk++) {
                const int k = k0 + kk;
                float2 wrz = ((const float2*)(wb + kk * KROW))[j];
                float  wn  = (wb + kk * KROW + 2 * JPAD)[j];
                u64 wr2 = dup2(wrz.x), wz2 = dup2(wrz.y), wn2 = dup2(wn);
                const ulonglong2* __restrict__ xq = (const ulonglong2*)(xT + k * XS);
                if (k < MSG_DIM) {
                    #pragma unroll
                    for (int q = 0; q < ROWS / 4; q++) {
                        ulonglong2 xv = xq[q];
                        ar2 [2*q]   = fma2(wr2, xv.x, ar2 [2*q]);
                        ar2 [2*q+1] = fma2(wr2, xv.y, ar2 [2*q+1]);
                        az2 [2*q]   = fma2(wz2, xv.x, az2 [2*q]);
                        az2 [2*q+1] = fma2(wz2, xv.y, az2 [2*q+1]);
                        ani2[2*q]   = fma2(wn2, xv.x, ani2[2*q]);
                        ani2[2*q+1] = fma2(wn2, xv.y, ani2[2*q+1]);
                    }
                } else {
                    #pragma unroll
                    for (int q = 0; q < ROWS / 4; q++) {
                        ulonglong2 xv = xq[q];
                        ar2 [2*q]   = fma2(wr2, xv.x, ar2 [2*q]);
                        ar2 [2*q+1] = fma2(wr2, xv.y, ar2 [2*q+1]);
                        az2 [2*q]   = fma2(wz2, xv.x, az2 [2*q]);
                        az2 [2*q+1] = fma2(wz2, xv.y, az2 [2*q+1]);
                        anh2[2*q]   = fma2(wn2, xv.x, anh2[2*q]);
                        anh2[2*q+1] = fma2(wn2, xv.y, anh2[2*q+1]);
                    }
                }
            }
        }
    }

    // ---- epilogue ----
    if (j < MEM_DIM) {
        const float br = g_bias[j];
        const float bz = g_bias[JPAD + j];
        const float bi = g_bias[2 * JPAD + j];
        const float bh = g_bias[3 * JPAD + j];

        #pragma unroll
        for (int p = 0; p < ROWS / 2; p++) {
            float2 arv = unpack2(ar2[p]);
            float2 azv = unpack2(az2[p]);
            float2 aiv = unpack2(ani2[p]);
            float2 ahv = unpack2(anh2[p]);
            #pragma unroll
            for (int s = 0; s < 2; s++) {
                int r = 2 * p + s;
                int nid = s_nid[r];
                if (nid < 0) continue;
                float a_r = (s ? arv.y : arv.x) + br;
                float a_z = (s ? azv.y : azv.x) + bz;
                float a_i = (s ? aiv.y : aiv.x) + bi;
                float a_h = (s ? ahv.y : ahv.x) + bh;
                float rg = 1.f / (1.f + expf(-a_r));
                float zg = 1.f / (1.f + expf(-a_z));
                float ng = tanhf(a_i + rg * a_h);
                float h_old = xT[(MSG_DIM + j) * XS + r];
                out[(size_t)nid * MEM_DIM + j] = (1.f - zg) * ng + zg * h_old;
            }
        }
    }

    if (tid < ROWS && s_nid[tid] >= 0) {
        out[(size_t)n_nodes * MEM_DIM + s_nid[tid]] = s_ts[tid];
    }
}

// ---------------------------------------------------------------------------
extern "C" void kernel_launch(void* const* d_in, const int* in_sizes, int n_in,
                              void* d_out, int out_size) {
    const int*   node_ids    = (const int*)  d_in[0];
    const float* messages    = (const float*)d_in[1];
    const float* timestamps  = (const float*)d_in[2];
    const float* memory      = (const float*)d_in[3];
    const float* last_update = (const float*)d_in[4];
    const float* W_ih        = (const float*)d_in[5];
    const float* W_hh        = (const float*)d_in[6];
    const float* b_ih        = (const float*)d_in[7];
    const float* b_hh        = (const float*)d_in[8];
    float* out = (float*)d_out;

    const int       n_upd   = in_sizes[0];
    const long long n_nodes = in_sizes[4];
    const long long nmem    = n_nodes * (long long)MEM_DIM;

    static int smem_set = 0;
    if (!smem_set) {
        cudaFuncSetAttribute(gru_kernel,
                             cudaFuncAttributeMaxDynamicSharedMemorySize, SM_TOT);
        smem_set = 1;
    }

    prep_kernel<<<(KDIM * JPAD + 255) / 256, 256>>>(W_ih, W_hh, b_ih, b_hh);

    {
        long long n4 = (nmem + 3) >> 2;
        copy_kernel<<<(unsigned)((n4 + 255) / 256), 256>>>(memory, out, nmem);
        long long n4b = (n_nodes + 3) >> 2;
        copy_kernel<<<(unsigned)((n4b + 255) / 256), 256>>>(last_update, out + nmem, n_nodes);
    }

    gru_kernel<<<(n_upd + ROWS - 1) / ROWS, NTHREADS, SM_TOT>>>(
        node_ids, messages, timestamps, memory, out, n_upd, n_nodes);
}

// round 8
// speedup vs baseline: 1.2162x; 1.2162x over previous
#include <cuda_runtime.h>
#include <math.h>

typedef unsigned long long u64;

#define MSG_DIM 100
#define MEM_DIM 172
#define KDIM    272          // MSG_DIM + MEM_DIM
#define JPAD    176          // MEM_DIM padded
#define ROWS    16           // rows (update entries) per block
#define NTHREADS 192
#define XSTRIDE 20           // smem row stride (floats), 16B-aligned
#define NGRP    68           // KDIM / 4 k-groups
#define NGRP1   25           // groups with k < 100 (i_n phase)

// ---------------------------------------------------------------------------
// Persistent scratch: weights repacked K-major (merged n plane) + bias.
// ~574 KB total -> L2 resident, fully coalesced reads in the main loop.
// ---------------------------------------------------------------------------
__device__ float g_Wr[KDIM * JPAD];   // r-gate  (k<100: W_ih | k>=100: W_hh)
__device__ float g_Wz[KDIM * JPAD];   // z-gate
__device__ float g_Wn[KDIM * JPAD];   // n-gate  (k<100: i_n | k>=100: h_n)
__device__ float g_bias[4 * JPAD];    // br, bz, bin, bhn

// ---- packed fp32x2 helpers -------------------------------------------------
__device__ __forceinline__ u64 fma2(u64 b, u64 x, u64 c) {
    u64 d;
    asm("fma.rn.f32x2 %0, %1, %2, %3;" : "=l"(d) : "l"(b), "l"(x), "l"(c));
    return d;
}
__device__ __forceinline__ u64 dup2(float v) {
    u64 d; unsigned u = __float_as_uint(v);
    asm("mov.b64 %0, {%1, %1};" : "=l"(d) : "r"(u));
    return d;
}
__device__ __forceinline__ float2 unpack2(u64 d) {
    unsigned lo, hi;
    asm("mov.b64 {%0, %1}, %2;" : "=r"(lo), "=r"(hi) : "l"(d));
    return make_float2(__uint_as_float(lo), __uint_as_float(hi));
}

// ---------------------------------------------------------------------------
// Prep: repack W_ih [516,100], W_hh [516,172] into K-major planes + bias.
// ---------------------------------------------------------------------------
__global__ void prep_kernel(const float* __restrict__ W_ih,
                            const float* __restrict__ W_hh,
                            const float* __restrict__ b_ih,
                            const float* __restrict__ b_hh) {
    int idx = blockIdx.x * blockDim.x + threadIdx.x;
    if (idx < KDIM * JPAD) {
        int k = idx / JPAD;
        int j = idx - k * JPAD;
        float wr = 0.f, wz = 0.f, wn = 0.f;
        if (j < MEM_DIM) {
            if (k < MSG_DIM) {
                wr = W_ih[j * MSG_DIM + k];
                wz = W_ih[(MEM_DIM + j) * MSG_DIM + k];
                wn = W_ih[(2 * MEM_DIM + j) * MSG_DIM + k];
            } else {
                int kk = k - MSG_DIM;
                wr = W_hh[j * MEM_DIM + kk];
                wz = W_hh[(MEM_DIM + j) * MEM_DIM + kk];
                wn = W_hh[(2 * MEM_DIM + j) * MEM_DIM + kk];
            }
        }
        g_Wr[idx] = wr;
        g_Wz[idx] = wz;
        g_Wn[idx] = wn;
    }
    if (idx < JPAD) {
        int j = idx;
        float br = 0.f, bz = 0.f, bi = 0.f, bh = 0.f;
        if (j < MEM_DIM) {
            br = b_ih[j]               + b_hh[j];
            bz = b_ih[MEM_DIM + j]     + b_hh[MEM_DIM + j];
            bi = b_ih[2 * MEM_DIM + j];
            bh = b_hh[2 * MEM_DIM + j];
        }
        g_bias[j]            = br;
        g_bias[JPAD + j]     = bz;
        g_bias[2 * JPAD + j] = bi;
        g_bias[3 * JPAD + j] = bh;
    }
}

// ---------------------------------------------------------------------------
// Passthrough copy (vectorized). Full occupancy, MLP-rich.
// ---------------------------------------------------------------------------
__global__ void copy_kernel(const float* __restrict__ src, float* __restrict__ dst, long long n) {
    long long i = (long long)blockIdx.x * blockDim.x + threadIdx.x;
    long long n4 = n >> 2;
    if (i < n4) ((float4*)dst)[i] = ((const float4*)src)[i];
    long long tail = n & 3;
    if (i < tail) dst[n4 * 4 + i] = src[n4 * 4 + i];
}

// ---------------------------------------------------------------------------
// GRU inner helpers: k-groups of 4, register double-buffered weights.
// ---------------------------------------------------------------------------
__device__ __forceinline__ void load_group(float* __restrict__ buf, int g,
                                           const float* __restrict__ pr,
                                           const float* __restrict__ pz,
                                           const float* __restrict__ pn) {
    int gg = (g > NGRP - 1) ? (NGRP - 1) : g;   // clamp (harmless re-load)
    int kb = 4 * gg;
    #pragma unroll
    for (int t = 0; t < 4; t++) {
        buf[t]     = __ldg(pr + (kb + t) * JPAD);
        buf[4 + t] = __ldg(pz + (kb + t) * JPAD);
        buf[8 + t] = __ldg(pn + (kb + t) * JPAD);
    }
}

__device__ __forceinline__ void compute_group(const float* __restrict__ buf, int g,
                                              const float (*__restrict__ xT)[XSTRIDE],
                                              u64* __restrict__ ar2,
                                              u64* __restrict__ az2,
                                              u64* __restrict__ an2) {
    #pragma unroll
    for (int kk = 0; kk < 4; kk++) {
        int k = 4 * g + kk;
        u64 wr2 = dup2(buf[kk]);
        u64 wz2 = dup2(buf[4 + kk]);
        u64 wn2 = dup2(buf[8 + kk]);
        const ulonglong2* __restrict__ xq = (const ulonglong2*)&xT[k][0];
        #pragma unroll
        for (int q = 0; q < 4; q++) {
            ulonglong2 xv = xq[q];
            ar2[2*q]   = fma2(wr2, xv.x, ar2[2*q]);
            ar2[2*q+1] = fma2(wr2, xv.y, ar2[2*q+1]);
            az2[2*q]   = fma2(wz2, xv.x, az2[2*q]);
            az2[2*q+1] = fma2(wz2, xv.y, az2[2*q+1]);
            an2[2*q]   = fma2(wn2, xv.x, an2[2*q]);
            an2[2*q+1] = fma2(wn2, xv.y, an2[2*q+1]);
        }
    }
}

// ---------------------------------------------------------------------------
// Fused gather + GRU GEMM + elementwise + scatter.
// Thread j (<172) owns output column j across 16 rows; accumulators hold
// 2 rows per f32x2 register. Weight k-groups double-buffered in registers.
// ---------------------------------------------------------------------------
__global__ void __launch_bounds__(NTHREADS, 3)
gru_kernel(const int*   __restrict__ node_ids,
           const float* __restrict__ messages,
           const float* __restrict__ timestamps,
           const float* __restrict__ memory,
           float*       __restrict__ out,
           int n_upd, long long n_nodes)
{
    __shared__ __align__(16) float xT[KDIM][XSTRIDE];   // transposed [k][row]
    __shared__ int   s_nid[ROWS];
    __shared__ float s_ts [ROWS];

    const int tid  = threadIdx.x;
    const int row0 = blockIdx.x * ROWS;

    if (tid < ROWS) {
        int r = row0 + tid;
        if (r < n_upd) { s_nid[tid] = node_ids[r]; s_ts[tid] = timestamps[r]; }
        else           { s_nid[tid] = -1;          s_ts[tid] = 0.f; }
    }
    __syncthreads();

    // Gather x = [msg | h] transposed into smem. Coalesced global reads.
    for (int idx = tid; idx < ROWS * KDIM; idx += NTHREADS) {
        int r = idx / KDIM;
        int k = idx - r * KDIM;
        float v = 0.f;
        int nid = s_nid[r];
        if (nid >= 0) {
            v = (k < MSG_DIM)
              ? messages[(size_t)(row0 + r) * MSG_DIM + k]
              : memory  [(size_t)nid * MEM_DIM + (k - MSG_DIM)];
        }
        xT[k][r] = v;
    }
    __syncthreads();

    const int j = tid;
    if (j < MEM_DIM) {
        u64 ar2[ROWS / 2], az2[ROWS / 2], ani2[ROWS / 2], anh2[ROWS / 2];
        u64 z0 = dup2(0.f);
        #pragma unroll
        for (int p = 0; p < ROWS / 2; p++) { ar2[p] = z0; az2[p] = z0; ani2[p] = z0; anh2[p] = z0; }

        const float* __restrict__ pr = g_Wr + j;
        const float* __restrict__ pz = g_Wz + j;
        const float* __restrict__ pn = g_Wn + j;

        float A[12], B[12];
        load_group(A, 0, pr, pz, pn);
        load_group(B, 1, pr, pz, pn);

        // ---- Phase 1: groups 0..24 (k < 100) -> accumulate n into ani ----
        #pragma unroll 1
        for (int g = 0; g < NGRP1 - 1; g += 2) {      // g = 0,2,...,22
            compute_group(A, g,     xT, ar2, az2, ani2);
            load_group(A, g + 2, pr, pz, pn);
            compute_group(B, g + 1, xT, ar2, az2, ani2);
            load_group(B, g + 3, pr, pz, pn);
        }
        // A holds g24, B holds g25
        compute_group(A, NGRP1 - 1, xT, ar2, az2, ani2);   // g24 (k 96..99)
        load_group(A, NGRP1 + 1, pr, pz, pn);              // A <- g26

        // ---- Phase 2: groups 25..67 (k >= 100) -> accumulate n into anh ----
        #pragma unroll 1
        for (int g = NGRP1; g < NGRP - 2; g += 2) {   // g = 25,27,...,65
            compute_group(B, g,     xT, ar2, az2, anh2);
            load_group(B, g + 2, pr, pz, pn);
            compute_group(A, g + 1, xT, ar2, az2, anh2);
            load_group(A, g + 3, pr, pz, pn);
        }
        // B holds g67
        compute_group(B, NGRP - 1, xT, ar2, az2, anh2);

        const float br = g_bias[j];
        const float bz = g_bias[JPAD + j];
        const float bi = g_bias[2 * JPAD + j];
        const float bh = g_bias[3 * JPAD + j];

        #pragma unroll
        for (int p = 0; p < ROWS / 2; p++) {
            float2 arv = unpack2(ar2[p]);
            float2 azv = unpack2(az2[p]);
            float2 aiv = unpack2(ani2[p]);
            float2 ahv = unpack2(anh2[p]);
            #pragma unroll
            for (int s = 0; s < 2; s++) {
                int r = 2 * p + s;
                int nid = s_nid[r];
                if (nid < 0) continue;
                float a_r = (s ? arv.y : arv.x) + br;
                float a_z = (s ? azv.y : azv.x) + bz;
                float a_i = (s ? aiv.y : aiv.x) + bi;
                float a_h = (s ? ahv.y : ahv.x) + bh;
                float rg = 1.f / (1.f + expf(-a_r));
                float zg = 1.f / (1.f + expf(-a_z));
                float ng = tanhf(a_i + rg * a_h);
                float h_old = xT[MSG_DIM + j][r];
                out[(size_t)nid * MEM_DIM + j] = (1.f - zg) * ng + zg * h_old;
            }
        }
    }

    if (tid < ROWS && s_nid[tid] >= 0) {
        out[(size_t)n_nodes * MEM_DIM + s_nid[tid]] = s_ts[tid];
    }
}

// ---------------------------------------------------------------------------
extern "C" void kernel_launch(void* const* d_in, const int* in_sizes, int n_in,
                              void* d_out, int out_size) {
    const int*   node_ids    = (const int*)  d_in[0];
    const float* messages    = (const float*)d_in[1];
    const float* timestamps  = (const float*)d_in[2];
    const float* memory      = (const float*)d_in[3];
    const float* last_update = (const float*)d_in[4];
    const float* W_ih        = (const float*)d_in[5];
    const float* W_hh        = (const float*)d_in[6];
    const float* b_ih        = (const float*)d_in[7];
    const float* b_hh        = (const float*)d_in[8];
    float* out = (float*)d_out;

    const int       n_upd   = in_sizes[0];
    const long long n_nodes = in_sizes[4];
    const long long nmem    = n_nodes * (long long)MEM_DIM;

    // Repack weights (tiny)
    prep_kernel<<<(KDIM * JPAD + 255) / 256, 256>>>(W_ih, W_hh, b_ih, b_hh);

    // Passthrough copy: memory, then last_update
    {
        long long n4 = (nmem + 3) >> 2;
        copy_kernel<<<(unsigned)((n4 + 255) / 256), 256>>>(memory, out, nmem);
        long long n4b = (n_nodes + 3) >> 2;
        copy_kernel<<<(unsigned)((n4b + 255) / 256), 256>>>(last_update, out + nmem, n_nodes);
    }

    // Fused gather + GRU + scatter (after copy in-stream, so scatter wins)
    gru_kernel<<<(n_upd + ROWS - 1) / ROWS, NTHREADS>>>(
        node_ids, messages, timestamps, memory, out, n_upd, n_nodes);
}